// round 1
// baseline (speedup 1.0000x reference)
#include <cuda_runtime.h>
#include <cstdint>
#include <cstddef>

// Problem shape (fixed per reference setup_inputs)
#define Bb 4
#define Ss 4096
#define Dd 1024
#define Mm (Bb * Ss)   // 16384
#define Nn (2 * Dd)    // 2048
#define Kk (Dd)        // 1024

// Scratch for hg = x @ W^T : [16384, 2048] fp32 = 128 MiB (static, allowed)
__device__ float g_hg[(size_t)Mm * (size_t)Nn];

// ---------------------------------------------------------------------------
// Kernel 1: SGEMM  C[m,e] = sum_k A[m,k] * W[e,k]
// A row-major [M,K], W row-major [N,K]  (both K-contiguous -> symmetric loads)
// 128x128 tile, K-tile 8, 256 threads, 8x8 per-thread microkernel.
// ---------------------------------------------------------------------------
__global__ __launch_bounds__(256, 2) void sgemm_kernel(
    const float* __restrict__ A,
    const float* __restrict__ W)
{
    __shared__ float As[8][128];
    __shared__ float Bs[8][128];

    const int bm = blockIdx.y * 128;
    const int bn = blockIdx.x * 128;
    const int tid = threadIdx.x;

    // Global-load assignment: each thread loads one float4 of A and one of W
    const int lr = tid >> 1;          // 0..127 (row within tile)
    const int lc = (tid & 1) * 4;     // 0 or 4 (k offset)

    // Microkernel assignment: 16x16 thread grid, 8x8 outputs each
    const int cx = tid & 15;          // column group
    const int cy = tid >> 4;          // row group

    const float* Aptr = A + (size_t)(bm + lr) * Kk + lc;
    const float* Wptr = W + (size_t)(bn + lr) * Kk + lc;

    float acc[8][8];
#pragma unroll
    for (int i = 0; i < 8; i++)
#pragma unroll
        for (int j = 0; j < 8; j++) acc[i][j] = 0.0f;

    for (int k0 = 0; k0 < Kk; k0 += 8) {
        float4 a4 = *(const float4*)(Aptr + k0);
        float4 b4 = *(const float4*)(Wptr + k0);

        As[lc + 0][lr] = a4.x;
        As[lc + 1][lr] = a4.y;
        As[lc + 2][lr] = a4.z;
        As[lc + 3][lr] = a4.w;
        Bs[lc + 0][lr] = b4.x;
        Bs[lc + 1][lr] = b4.y;
        Bs[lc + 2][lr] = b4.z;
        Bs[lc + 3][lr] = b4.w;
        __syncthreads();

#pragma unroll
        for (int k = 0; k < 8; k++) {
            float4 ar0 = *(const float4*)&As[k][cy * 8];
            float4 ar1 = *(const float4*)&As[k][cy * 8 + 4];
            float4 br0 = *(const float4*)&Bs[k][cx * 8];
            float4 br1 = *(const float4*)&Bs[k][cx * 8 + 4];
            float a[8] = {ar0.x, ar0.y, ar0.z, ar0.w, ar1.x, ar1.y, ar1.z, ar1.w};
            float b[8] = {br0.x, br0.y, br0.z, br0.w, br1.x, br1.y, br1.z, br1.w};
#pragma unroll
            for (int i = 0; i < 8; i++)
#pragma unroll
                for (int j = 0; j < 8; j++)
                    acc[i][j] = fmaf(a[i], b[j], acc[i][j]);
        }
        __syncthreads();
    }

    // Write 8x8 tile (two float4 stores per row)
#pragma unroll
    for (int i = 0; i < 8; i++) {
        float* Crow = g_hg + (size_t)(bm + cy * 8 + i) * Nn + bn + cx * 8;
        float4 v0 = make_float4(acc[i][0], acc[i][1], acc[i][2], acc[i][3]);
        float4 v1 = make_float4(acc[i][4], acc[i][5], acc[i][6], acc[i][7]);
        *(float4*)(Crow)     = v0;
        *(float4*)(Crow + 4) = v1;
    }
}

// ---------------------------------------------------------------------------
// Kernel 2: linear-space scan.
//   a_t = sigmoid(-gate_t), v_t = sigmoid(gate_t) * g(hidden_t)
//   h_t = a_t * h_{t-1} + v_t           (== exp of the Heinsen log-space scan)
// One thread per (b, d) channel: 4096 threads total, coalesced across d.
// ---------------------------------------------------------------------------
__global__ __launch_bounds__(32) void scan_kernel(float* __restrict__ out)
{
    const int ch = blockIdx.x * blockDim.x + threadIdx.x;  // 0..4095
    const int b = ch >> 10;          // / Dd
    const int d = ch & (Dd - 1);     // % Dd

    const float* hg_base = g_hg + (size_t)b * Ss * Nn;
    float* out_base = out + (size_t)b * Ss * Dd;

    float h = 0.0f;
#pragma unroll 8
    for (int t = 0; t < Ss; t++) {
        const float* row = hg_base + (size_t)t * Nn;
        float hid = row[d];
        float gt  = row[Dd + d];

        // a = sigmoid(-gt): stable for all gt (expf(+inf) -> inf -> a=0)
        float a = __fdividef(1.0f, 1.0f + __expf(gt));
        // z = sigmoid(gt): stable for all gt
        float z = __fdividef(1.0f, 1.0f + __expf(-gt));
        // g(hid) = hid + 0.5 for hid >= 0, sigmoid(hid) otherwise
        float g = (hid >= 0.0f) ? (hid + 0.5f)
                                : __fdividef(1.0f, 1.0f + __expf(-hid));

        h = fmaf(a, h, z * g);
        out_base[(size_t)t * Dd + d] = h;
    }
}

// ---------------------------------------------------------------------------
extern "C" void kernel_launch(void* const* d_in, const int* in_sizes, int n_in,
                              void* d_out, int out_size)
{
    const float* x = (const float*)d_in[0];   // [4,4096,1024] -> [16384,1024]
    const float* W = (const float*)d_in[1];   // [2048,1024]
    float* out = (float*)d_out;               // [4,4096,1024]

    dim3 grid(Nn / 128, Mm / 128);            // (16, 128)
    sgemm_kernel<<<grid, 256>>>(x, W);

    scan_kernel<<<128, 32>>>(out);
}

// round 3
// speedup vs baseline: 3.3693x; 3.3693x over previous
#include <cuda_runtime.h>
#include <cuda_bf16.h>
#include <cstdint>
#include <cstddef>

// ---------------------------------------------------------------------------
// Shapes (fixed per reference)
// ---------------------------------------------------------------------------
#define Bb 4
#define Ss 4096
#define Dd 1024
#define Mm (Bb * Ss)   // 16384
#define Nn (2 * Dd)    // 2048
#define Kk (Dd)        // 1024

// GEMM tiling
#define TM 128
#define TN 128
#define TKC 32               // K elements per pipeline chunk
#define NKC (Kk / TKC)       // 32 chunks
#define NSTAGE 3

// Scan chunking
#define NCH 4096             // channels = Bb*Dd
#define CLEN 64
#define NCHUNK (Ss / CLEN)   // 64

// ---------------------------------------------------------------------------
// Static device scratch (allocation-free rule)
// ---------------------------------------------------------------------------
__device__ float          g_hg[(size_t)Mm * Nn];       // 128 MiB
__device__ __nv_bfloat16  g_Ah[(size_t)Mm * Kk];       // 32 MiB
__device__ __nv_bfloat16  g_Al[(size_t)Mm * Kk];       // 32 MiB
__device__ __nv_bfloat16  g_Wh[(size_t)Nn * Kk];       // 4 MiB
__device__ __nv_bfloat16  g_Wl[(size_t)Nn * Kk];       // 4 MiB
__device__ float          g_Achk[NCHUNK * NCH];
__device__ float          g_Hend[NCHUNK * NCH];
__device__ float          g_Hin [NCHUNK * NCH];

// ---------------------------------------------------------------------------
// PTX helpers (sm_103 baseline features only: cp.async, ldmatrix, mma.sync)
// ---------------------------------------------------------------------------
__device__ __forceinline__ uint32_t smem_u32(const void* p) {
    return (uint32_t)__cvta_generic_to_shared(p);
}

#define CP_ASYNC16(s, g) \
    asm volatile("cp.async.cg.shared.global [%0], [%1], 16;\n" :: "r"(s), "l"(g))
#define CP_COMMIT() asm volatile("cp.async.commit_group;\n" ::: "memory")
#define CP_WAIT(n)  asm volatile("cp.async.wait_group %0;\n" :: "n"(n) : "memory")

#define LDSM_X4(r0, r1, r2, r3, a)                                              \
    asm volatile("ldmatrix.sync.aligned.m8n8.x4.shared.b16 {%0,%1,%2,%3}, [%4];" \
                 : "=r"(r0), "=r"(r1), "=r"(r2), "=r"(r3) : "r"(a))

#define MMA16816(d, a, b)                                                       \
    asm volatile("mma.sync.aligned.m16n8k16.row.col.f32.bf16.bf16.f32 "         \
                 "{%0,%1,%2,%3}, {%4,%5,%6,%7}, {%8,%9}, {%0,%1,%2,%3};"        \
                 : "+f"((d)[0]), "+f"((d)[1]), "+f"((d)[2]), "+f"((d)[3])       \
                 : "r"((a)[0]), "r"((a)[1]), "r"((a)[2]), "r"((a)[3]),          \
                   "r"((b)[0]), "r"((b)[1]))

// ---------------------------------------------------------------------------
// Kernel 0: fp32 -> (bf16 hi, bf16 lo) split for x and W
// ---------------------------------------------------------------------------
__device__ __forceinline__ void split_store(__nv_bfloat16* H, __nv_bfloat16* L,
                                            size_t i, float4 v) {
    float f[4] = {v.x, v.y, v.z, v.w};
    unsigned short hs[4], ls[4];
#pragma unroll
    for (int k = 0; k < 4; k++) {
        __nv_bfloat16 h = __float2bfloat16_rn(f[k]);
        __nv_bfloat16 l = __float2bfloat16_rn(f[k] - __bfloat162float(h));
        hs[k] = __bfloat16_as_ushort(h);
        ls[k] = __bfloat16_as_ushort(l);
    }
    uint2 H2 = make_uint2((uint32_t)hs[0] | ((uint32_t)hs[1] << 16),
                          (uint32_t)hs[2] | ((uint32_t)hs[3] << 16));
    uint2 L2 = make_uint2((uint32_t)ls[0] | ((uint32_t)ls[1] << 16),
                          (uint32_t)ls[2] | ((uint32_t)ls[3] << 16));
    *(uint2*)(H + 4 * i) = H2;
    *(uint2*)(L + 4 * i) = L2;
}

__global__ __launch_bounds__(256) void split_kernel(const float* __restrict__ x,
                                                    const float* __restrict__ w) {
    const size_t NX4 = (size_t)Mm * Kk / 4;
    const size_t NW4 = (size_t)Nn * Kk / 4;
    size_t i = (size_t)blockIdx.x * 256 + threadIdx.x;
    if (i < NX4) {
        split_store(g_Ah, g_Al, i, ((const float4*)x)[i]);
    } else if (i < NX4 + NW4) {
        size_t j = i - NX4;
        split_store(g_Wh, g_Wl, j, ((const float4*)w)[j]);
    }
}

// ---------------------------------------------------------------------------
// Kernel 1: bf16 3-split GEMM via mma.sync.  g_hg[M,N] = x @ W^T (fp32 accum)
// CTA 128x128, warp grid 2x4 (warp tile 64x32), K chunk 32, 3-stage cp.async.
//
// smem stage layout (32 KB): Ah[128][32] Al Wh Wl, each 8 KB, row = 64 B,
// 16B-chunk swizzle: chunk' = chunk ^ ((row>>1)&3)  -> conflict-free ldmatrix.
// ---------------------------------------------------------------------------
#define SOFF_AH 0
#define SOFF_AL 8192
#define SOFF_WH 16384
#define SOFF_WL 24576
#define STAGE_BYTES 32768
#define SMEM_DYN (NSTAGE * STAGE_BYTES)

__device__ __forceinline__ uint32_t sw_off(int row, int chunk) {
    return (uint32_t)(row * 64 + ((chunk ^ ((row >> 1) & 3)) << 4));
}

__device__ __forceinline__ void load_stage(int kc, uint32_t sb, int bm, int bn, int tid) {
    const int k0 = kc * TKC;
#pragma unroll
    for (int j = 0; j < 2; j++) {
        int q = tid + j * 256;          // 0..511
        int row = q >> 2;               // 0..127
        int ch = q & 3;                 // 16B chunk within 64B row
        uint32_t so = sw_off(row, ch);
        size_t ga = (size_t)(bm + row) * Kk + k0 + ch * 8;
        size_t gw = (size_t)(bn + row) * Kk + k0 + ch * 8;
        CP_ASYNC16(sb + SOFF_AH + so, g_Ah + ga);
        CP_ASYNC16(sb + SOFF_AL + so, g_Al + ga);
        CP_ASYNC16(sb + SOFF_WH + so, g_Wh + gw);
        CP_ASYNC16(sb + SOFF_WL + so, g_Wl + gw);
    }
    CP_COMMIT();
}

__global__ __launch_bounds__(256, 2) void gemm_kernel() {
    extern __shared__ char smraw[];
    const uint32_t sm0 = smem_u32(smraw);

    const int tid = threadIdx.x;
    const int wid = tid >> 5;
    const int lane = tid & 31;
    const int bm = blockIdx.y * TM;
    const int bn = blockIdx.x * TN;

    const int warp_m = (wid & 1) * 64;   // 0 / 64
    const int warp_n = (wid >> 1) * 32;  // 0 / 32 / 64 / 96

    // ldmatrix lane addressing: rows (lane&15), 16B half select (lane>>4)
    const int lrow = lane & 15;
    const int lsel = lane >> 4;

    float acc[4][4][4];
#pragma unroll
    for (int i = 0; i < 4; i++)
#pragma unroll
        for (int j = 0; j < 4; j++)
#pragma unroll
            for (int r = 0; r < 4; r++) acc[i][j][r] = 0.0f;

    load_stage(0, sm0, bm, bn, tid);
    load_stage(1, sm0 + STAGE_BYTES, bm, bn, tid);
    load_stage(2, sm0 + 2 * STAGE_BYTES, bm, bn, tid);

    for (int kc = 0; kc < NKC; kc++) {
        const uint32_t sb = sm0 + (uint32_t)(kc % NSTAGE) * STAGE_BYTES;
        CP_WAIT(NSTAGE - 1);
        __syncthreads();

#pragma unroll
        for (int ks = 0; ks < 2; ks++) {
            // ---- load fragments for this k16 step ----
            uint32_t aH[4][4], aL[4][4], bH[4][2], bL[4][2];
#pragma unroll
            for (int mt = 0; mt < 4; mt++) {
                int row = warp_m + mt * 16 + lrow;
                int chunk = 2 * ks + lsel;
                uint32_t so = sw_off(row, chunk);
                LDSM_X4(aH[mt][0], aH[mt][1], aH[mt][2], aH[mt][3], sb + SOFF_AH + so);
                LDSM_X4(aL[mt][0], aL[mt][1], aL[mt][2], aL[mt][3], sb + SOFF_AL + so);
            }
#pragma unroll
            for (int ng = 0; ng < 2; ng++) {
                int row = warp_n + ng * 16 + lrow;
                int chunk = 2 * ks + lsel;
                uint32_t so = sw_off(row, chunk);
                uint32_t r0, r1, r2, r3;
                // x4 matrices: (n0-7,k0-7),(n8-15,k0-7),(n0-7,k8-15),(n8-15,k8-15)
                LDSM_X4(r0, r1, r2, r3, sb + SOFF_WH + so);
                bH[ng * 2 + 0][0] = r0; bH[ng * 2 + 0][1] = r2;
                bH[ng * 2 + 1][0] = r1; bH[ng * 2 + 1][1] = r3;
                LDSM_X4(r0, r1, r2, r3, sb + SOFF_WL + so);
                bL[ng * 2 + 0][0] = r0; bL[ng * 2 + 0][1] = r2;
                bL[ng * 2 + 1][0] = r1; bL[ng * 2 + 1][1] = r3;
            }
            // ---- 3-product MMAs ----
#pragma unroll
            for (int mt = 0; mt < 4; mt++)
#pragma unroll
                for (int nt = 0; nt < 4; nt++) {
                    MMA16816(acc[mt][nt], aH[mt], bH[nt]);
                    MMA16816(acc[mt][nt], aH[mt], bL[nt]);
                    MMA16816(acc[mt][nt], aL[mt], bH[nt]);
                }
        }
        __syncthreads();
        if (kc + NSTAGE < NKC) load_stage(kc + NSTAGE, sb, bm, bn, tid);
    }

    // Epilogue: c-frag (m16n8): c0,c1 -> row=lane/4, cols=(lane%4)*2; c2,c3 -> row+8
    const int erow = lane >> 2;
    const int ecol = (lane & 3) * 2;
#pragma unroll
    for (int mt = 0; mt < 4; mt++)
#pragma unroll
        for (int nt = 0; nt < 4; nt++) {
            int row = bm + warp_m + mt * 16 + erow;
            int col = bn + warp_n + nt * 8 + ecol;
            *(float2*)(g_hg + (size_t)row * Nn + col) =
                make_float2(acc[mt][nt][0], acc[mt][nt][1]);
            *(float2*)(g_hg + (size_t)(row + 8) * Nn + col) =
                make_float2(acc[mt][nt][2], acc[mt][nt][3]);
        }
}

// ---------------------------------------------------------------------------
// Scan: h_t = sigmoid(-g_t) * h_{t-1} + sigmoid(g_t) * g(hidden_t)
// (exp of the reference's log-space Heinsen scan; all terms positive)
// ---------------------------------------------------------------------------
__device__ __forceinline__ void gate_math(float gt, float hid, float& a, float& v) {
    float q = __expf(-fabsf(gt));                // in (0,1]
    float r = __fdividef(1.0f, 1.0f + q);        // sigmoid(|gt|)
    float z, aa;
    if (gt >= 0.0f) { z = r;     aa = q * r; }   // z=sig(gt), a=sig(-gt)
    else            { z = q * r; aa = r;     }
    float g;
    if (hid >= 0.0f) g = hid + 0.5f;
    else {
        float q2 = __expf(hid);
        g = __fdividef(q2, 1.0f + q2);
    }
    a = aa;
    v = z * g;
}

// Pass 1: per-chunk summaries (A = prod a, Hend = local scan end)
__global__ __launch_bounds__(256) void scan_pass1() {
    int idx = blockIdx.x * 256 + threadIdx.x;    // 262144
    int ch = idx & (NCH - 1);
    int c  = idx >> 12;
    int b = ch >> 10, d = ch & (Dd - 1);
    const float* row = g_hg + ((size_t)b * Ss + (size_t)c * CLEN) * Nn + d;
    float h = 0.0f, A = 1.0f;
#pragma unroll 4
    for (int t = 0; t < CLEN; t++) {
        float hid = row[0];
        float gt  = row[Dd];
        row += Nn;
        float a, v;
        gate_math(gt, hid, a, v);
        h = fmaf(a, h, v);
        A *= a;
    }
    g_Achk[c * NCH + ch] = A;
    g_Hend[c * NCH + ch] = h;
}

// Pass 2: scan over chunk summaries (carry-in per chunk)
__global__ __launch_bounds__(256) void scan_pass2() {
    int ch = blockIdx.x * 256 + threadIdx.x;     // 4096
    float Hin = 0.0f;
#pragma unroll 4
    for (int c = 0; c < NCHUNK; c++) {
        g_Hin[c * NCH + ch] = Hin;
        Hin = fmaf(g_Achk[c * NCH + ch], Hin, g_Hend[c * NCH + ch]);
    }
}

// Pass 3: full recompute seeded with carry-in, write output
__global__ __launch_bounds__(256) void scan_pass3(float* __restrict__ out) {
    int idx = blockIdx.x * 256 + threadIdx.x;
    int ch = idx & (NCH - 1);
    int c  = idx >> 12;
    int b = ch >> 10, d = ch & (Dd - 1);
    const float* row = g_hg + ((size_t)b * Ss + (size_t)c * CLEN) * Nn + d;
    float* orow = out + ((size_t)b * Ss + (size_t)c * CLEN) * Dd + d;
    float h = g_Hin[c * NCH + ch];
#pragma unroll 4
    for (int t = 0; t < CLEN; t++) {
        float hid = row[0];
        float gt  = row[Dd];
        row += Nn;
        float a, v;
        gate_math(gt, hid, a, v);
        h = fmaf(a, h, v);
        *orow = h;
        orow += Dd;
    }
}

// ---------------------------------------------------------------------------
extern "C" void kernel_launch(void* const* d_in, const int* in_sizes, int n_in,
                              void* d_out, int out_size)
{
    const float* x = (const float*)d_in[0];
    const float* W = (const float*)d_in[1];
    float* out = (float*)d_out;

    cudaFuncSetAttribute(gemm_kernel, cudaFuncAttributeMaxDynamicSharedMemorySize, SMEM_DYN);

    const int nsplit = (int)(((size_t)Mm * Kk / 4 + (size_t)Nn * Kk / 4) / 256);
    split_kernel<<<nsplit, 256>>>(x, W);

    gemm_kernel<<<dim3(Nn / TN, Mm / TM), 256, SMEM_DYN>>>();

    scan_pass1<<<(NCH * NCHUNK) / 256, 256>>>();
    scan_pass2<<<NCH / 256, 256>>>();
    scan_pass3<<<(NCH * NCHUNK) / 256, 256>>>(out);
}

// round 4
// speedup vs baseline: 4.6599x; 1.3831x over previous
#include <cuda_runtime.h>
#include <cuda_fp16.h>
#include <cstdint>
#include <cstddef>

// ---------------------------------------------------------------------------
// Shapes (fixed per reference)
// ---------------------------------------------------------------------------
#define Bb 4
#define Ss 4096
#define Dd 1024
#define Mm (Bb * Ss)   // 16384
#define Nn (2 * Dd)    // 2048
#define Kk (Dd)        // 1024

// GEMM tiling
#define TM 128
#define TN 128
#define TKC 32               // K elements per pipeline chunk
#define NKC (Kk / TKC)       // 32 chunks
#define NSTAGE 4

// Scan chunking
#define NCH 4096             // channels = Bb*Dd
#define CLEN 64
#define NCHUNK (Ss / CLEN)   // 64

// ---------------------------------------------------------------------------
// Static device scratch (allocation-free rule)
// ---------------------------------------------------------------------------
__device__ float  g_hg[(size_t)Mm * Nn];      // 128 MiB
__device__ __half g_Ah[(size_t)Mm * Kk];      // 32 MiB  (fp16 hi of x)
__device__ __half g_Al[(size_t)Mm * Kk];      // 32 MiB  (fp16 lo of x)
__device__ __half g_Wh[(size_t)Nn * Kk];      // 4 MiB   (fp16 of W)
__device__ float  g_Achk[NCHUNK * NCH];
__device__ float  g_Hend[NCHUNK * NCH];
__device__ float  g_Hin [NCHUNK * NCH];

// ---------------------------------------------------------------------------
// PTX helpers (sm_103 baseline: cp.async, ldmatrix, mma.sync)
// ---------------------------------------------------------------------------
__device__ __forceinline__ uint32_t smem_u32(const void* p) {
    return (uint32_t)__cvta_generic_to_shared(p);
}

#define CP_ASYNC16(s, g) \
    asm volatile("cp.async.cg.shared.global [%0], [%1], 16;\n" :: "r"(s), "l"(g))
#define CP_COMMIT() asm volatile("cp.async.commit_group;\n" ::: "memory")
#define CP_WAIT(n)  asm volatile("cp.async.wait_group %0;\n" :: "n"(n) : "memory")

#define LDSM_X4(r0, r1, r2, r3, a)                                              \
    asm volatile("ldmatrix.sync.aligned.m8n8.x4.shared.b16 {%0,%1,%2,%3}, [%4];" \
                 : "=r"(r0), "=r"(r1), "=r"(r2), "=r"(r3) : "r"(a))

#define MMA16816F16(d, a, b)                                                    \
    asm volatile("mma.sync.aligned.m16n8k16.row.col.f32.f16.f16.f32 "           \
                 "{%0,%1,%2,%3}, {%4,%5,%6,%7}, {%8,%9}, {%0,%1,%2,%3};"        \
                 : "+f"((d)[0]), "+f"((d)[1]), "+f"((d)[2]), "+f"((d)[3])       \
                 : "r"((a)[0]), "r"((a)[1]), "r"((a)[2]), "r"((a)[3]),          \
                   "r"((b)[0]), "r"((b)[1]))

// ---------------------------------------------------------------------------
// Kernel 0: fp32 x -> (fp16 hi, fp16 lo); fp32 W -> fp16
// ---------------------------------------------------------------------------
__global__ __launch_bounds__(256) void split_kernel(const float* __restrict__ x,
                                                    const float* __restrict__ w) {
    const size_t NX4 = (size_t)Mm * Kk / 4;
    const size_t NW4 = (size_t)Nn * Kk / 4;
    size_t i = (size_t)blockIdx.x * 256 + threadIdx.x;
    if (i < NX4) {
        float4 v = ((const float4*)x)[i];
        float f[4] = {v.x, v.y, v.z, v.w};
        unsigned short hs[4], ls[4];
#pragma unroll
        for (int k = 0; k < 4; k++) {
            __half h = __float2half_rn(f[k]);
            __half l = __float2half_rn(f[k] - __half2float(h));
            hs[k] = __half_as_ushort(h);
            ls[k] = __half_as_ushort(l);
        }
        *(uint2*)(g_Ah + 4 * i) = make_uint2((uint32_t)hs[0] | ((uint32_t)hs[1] << 16),
                                             (uint32_t)hs[2] | ((uint32_t)hs[3] << 16));
        *(uint2*)(g_Al + 4 * i) = make_uint2((uint32_t)ls[0] | ((uint32_t)ls[1] << 16),
                                             (uint32_t)ls[2] | ((uint32_t)ls[3] << 16));
    } else if (i < NX4 + NW4) {
        size_t j = i - NX4;
        float4 v = ((const float4*)w)[j];
        unsigned short hs[4] = {
            __half_as_ushort(__float2half_rn(v.x)),
            __half_as_ushort(__float2half_rn(v.y)),
            __half_as_ushort(__float2half_rn(v.z)),
            __half_as_ushort(__float2half_rn(v.w))};
        *(uint2*)(g_Wh + 4 * j) = make_uint2((uint32_t)hs[0] | ((uint32_t)hs[1] << 16),
                                             (uint32_t)hs[2] | ((uint32_t)hs[3] << 16));
    }
}

// ---------------------------------------------------------------------------
// Kernel 1: fp16 2-product GEMM via mma.sync.  g_hg = x @ W^T (fp32 accum)
// CTA 128x128, warps 2x4 (warp tile 64x32), K chunk 32, 4-stage cp.async.
// smem stage (24 KB): Ah[128][32], Al, Wh; row=64B, 16B-chunk XOR swizzle.
// ---------------------------------------------------------------------------
#define SOFF_AH 0
#define SOFF_AL 8192
#define SOFF_WH 16384
#define STAGE_BYTES 24576
#define SMEM_DYN (NSTAGE * STAGE_BYTES)

__device__ __forceinline__ uint32_t sw_off(int row, int chunk) {
    return (uint32_t)(row * 64 + ((chunk ^ ((row >> 1) & 3)) << 4));
}

__device__ __forceinline__ void load_stage(int kc, uint32_t sb, int bm, int bn, int tid) {
    const int k0 = kc * TKC;
#pragma unroll
    for (int j = 0; j < 2; j++) {
        int q = tid + j * 256;          // 0..511
        int row = q >> 2;               // 0..127
        int ch = q & 3;                 // 16B chunk within 64B row
        uint32_t so = sw_off(row, ch);
        size_t ga = (size_t)(bm + row) * Kk + k0 + ch * 8;
        size_t gw = (size_t)(bn + row) * Kk + k0 + ch * 8;
        CP_ASYNC16(sb + SOFF_AH + so, g_Ah + ga);
        CP_ASYNC16(sb + SOFF_AL + so, g_Al + ga);
        CP_ASYNC16(sb + SOFF_WH + so, g_Wh + gw);
    }
    CP_COMMIT();
}

__global__ __launch_bounds__(256, 2) void gemm_kernel() {
    extern __shared__ char smraw[];
    const uint32_t sm0 = smem_u32(smraw);

    const int tid = threadIdx.x;
    const int wid = tid >> 5;
    const int lane = tid & 31;
    const int bm = blockIdx.y * TM;
    const int bn = blockIdx.x * TN;

    const int warp_m = (wid & 1) * 64;
    const int warp_n = (wid >> 1) * 32;

    const int lrow = lane & 15;
    const int lsel = lane >> 4;

    float acc[4][4][4];
#pragma unroll
    for (int i = 0; i < 4; i++)
#pragma unroll
        for (int j = 0; j < 4; j++)
#pragma unroll
            for (int r = 0; r < 4; r++) acc[i][j][r] = 0.0f;

    load_stage(0, sm0, bm, bn, tid);
    load_stage(1, sm0 + STAGE_BYTES, bm, bn, tid);
    load_stage(2, sm0 + 2 * STAGE_BYTES, bm, bn, tid);

    for (int kc = 0; kc < NKC; kc++) {
        const uint32_t sb = sm0 + (uint32_t)(kc % NSTAGE) * STAGE_BYTES;
        CP_WAIT(2);
        __syncthreads();
        if (kc + 3 < NKC)
            load_stage(kc + 3, sm0 + (uint32_t)((kc + 3) % NSTAGE) * STAGE_BYTES,
                       bm, bn, tid);

#pragma unroll
        for (int ks = 0; ks < 2; ks++) {
            uint32_t aH[4][4], aL[4][4], bH[4][2];
            const int chunk = 2 * ks + lsel;
#pragma unroll
            for (int mt = 0; mt < 4; mt++) {
                uint32_t so = sw_off(warp_m + mt * 16 + lrow, chunk);
                LDSM_X4(aH[mt][0], aH[mt][1], aH[mt][2], aH[mt][3], sb + SOFF_AH + so);
                LDSM_X4(aL[mt][0], aL[mt][1], aL[mt][2], aL[mt][3], sb + SOFF_AL + so);
            }
#pragma unroll
            for (int ng = 0; ng < 2; ng++) {
                uint32_t so = sw_off(warp_n + ng * 16 + lrow, chunk);
                uint32_t r0, r1, r2, r3;
                LDSM_X4(r0, r1, r2, r3, sb + SOFF_WH + so);
                bH[ng * 2 + 0][0] = r0; bH[ng * 2 + 0][1] = r2;
                bH[ng * 2 + 1][0] = r1; bH[ng * 2 + 1][1] = r3;
            }
#pragma unroll
            for (int mt = 0; mt < 4; mt++)
#pragma unroll
                for (int nt = 0; nt < 4; nt++) {
                    MMA16816F16(acc[mt][nt], aH[mt], bH[nt]);
                    MMA16816F16(acc[mt][nt], aL[mt], bH[nt]);
                }
        }
        // next iteration's leading sync protects buffer reuse
    }

    const int erow = lane >> 2;
    const int ecol = (lane & 3) * 2;
#pragma unroll
    for (int mt = 0; mt < 4; mt++)
#pragma unroll
        for (int nt = 0; nt < 4; nt++) {
            int row = bm + warp_m + mt * 16 + erow;
            int col = bn + warp_n + nt * 8 + ecol;
            *(float2*)(g_hg + (size_t)row * Nn + col) =
                make_float2(acc[mt][nt][0], acc[mt][nt][1]);
            *(float2*)(g_hg + (size_t)(row + 8) * Nn + col) =
                make_float2(acc[mt][nt][2], acc[mt][nt][3]);
        }
}

// ---------------------------------------------------------------------------
// Scan: h_t = sigmoid(-g_t) * h_{t-1} + sigmoid(g_t) * g(hidden_t)
// ---------------------------------------------------------------------------
__device__ __forceinline__ void gate_math(float gt, float hid, float& a, float& v) {
    float q = __expf(-fabsf(gt));
    float r = __fdividef(1.0f, 1.0f + q);
    float z, aa;
    if (gt >= 0.0f) { z = r;     aa = q * r; }
    else            { z = q * r; aa = r;     }
    float g;
    if (hid >= 0.0f) g = hid + 0.5f;
    else {
        float q2 = __expf(hid);
        g = __fdividef(q2, 1.0f + q2);
    }
    a = aa;
    v = z * g;
}

// Pass 1: per-chunk summaries (A = prod a, Hend = local scan from 0)
__global__ __launch_bounds__(256) void scan_pass1() {
    int idx = blockIdx.x * 256 + threadIdx.x;    // 262144
    int ch = idx & (NCH - 1);
    int c  = idx >> 12;
    int b = ch >> 10, d = ch & (Dd - 1);
    const float* row = g_hg + ((size_t)b * Ss + (size_t)c * CLEN) * Nn + d;
    float h = 0.0f, A = 1.0f;
#pragma unroll 4
    for (int t = 0; t < CLEN; t++) {
        float hid = row[0];
        float gt  = row[Dd];
        row += Nn;
        float a, v;
        gate_math(gt, hid, a, v);
        h = fmaf(a, h, v);
        A *= a;
    }
    g_Achk[c * NCH + ch] = A;
    g_Hend[c * NCH + ch] = h;
}

// Pass 2: warp-parallel scan over chunk summaries. One warp per channel,
// 2 chunks per lane; affine composition (A,H)∘(A',H') = (A·A', A'·H + H').
__global__ __launch_bounds__(256) void scan_pass2() {
    int warp = (blockIdx.x * 256 + threadIdx.x) >> 5;   // 0..4095 (channel)
    int lane = threadIdx.x & 31;
    int c0 = 2 * lane, c1 = c0 + 1;

    float A0 = g_Achk[c0 * NCH + warp];
    float H0 = g_Hend[c0 * NCH + warp];
    float A1 = g_Achk[c1 * NCH + warp];
    float H1 = g_Hend[c1 * NCH + warp];

    // pair compose (c0 then c1)
    float Ap = A0 * A1;
    float Hp = fmaf(A1, H0, H1);

    // inclusive warp scan
    float Ai = Ap, Hi = Hp;
#pragma unroll
    for (int d = 1; d < 32; d <<= 1) {
        float Au = __shfl_up_sync(0xFFFFFFFFu, Ai, d);
        float Hu = __shfl_up_sync(0xFFFFFFFFu, Hi, d);
        if (lane >= d) {
            Hi = fmaf(Ai, Hu, Hi);   // prev ∘ cur: H = Acur*Hprev + Hcur
            Ai = Au * Ai;
        }
    }
    // exclusive prefix (identity for lane 0)
    float Hex = __shfl_up_sync(0xFFFFFFFFu, Hi, 1);
    if (lane == 0) Hex = 0.0f;

    // carry-in for chunk c0 is Hex (h starts at 0); for c1 compose chunk c0
    g_Hin[c0 * NCH + warp] = Hex;
    g_Hin[c1 * NCH + warp] = fmaf(A0, Hex, H0);
}

// Pass 3: full recompute seeded with carry-in, write output
__global__ __launch_bounds__(256) void scan_pass3(float* __restrict__ out) {
    int idx = blockIdx.x * 256 + threadIdx.x;
    int ch = idx & (NCH - 1);
    int c  = idx >> 12;
    int b = ch >> 10, d = ch & (Dd - 1);
    const float* row = g_hg + ((size_t)b * Ss + (size_t)c * CLEN) * Nn + d;
    float* orow = out + ((size_t)b * Ss + (size_t)c * CLEN) * Dd + d;
    float h = g_Hin[c * NCH + ch];
#pragma unroll 4
    for (int t = 0; t < CLEN; t++) {
        float hid = row[0];
        float gt  = row[Dd];
        row += Nn;
        float a, v;
        gate_math(gt, hid, a, v);
        h = fmaf(a, h, v);
        *orow = h;
        orow += Dd;
    }
}

// ---------------------------------------------------------------------------
extern "C" void kernel_launch(void* const* d_in, const int* in_sizes, int n_in,
                              void* d_out, int out_size)
{
    const float* x = (const float*)d_in[0];
    const float* W = (const float*)d_in[1];
    float* out = (float*)d_out;

    cudaFuncSetAttribute(gemm_kernel, cudaFuncAttributeMaxDynamicSharedMemorySize, SMEM_DYN);

    const int nsplit = (int)(((size_t)Mm * Kk / 4 + (size_t)Nn * Kk / 4) / 256);
    split_kernel<<<nsplit, 256>>>(x, W);

    gemm_kernel<<<dim3(Nn / TN, Mm / TM), 256, SMEM_DYN>>>();

    scan_pass1<<<(NCH * NCHUNK) / 256, 256>>>();
    scan_pass2<<<(NCH * 32) / 256, 256>>>();
    scan_pass3<<<(NCH * NCHUNK) / 256, 256>>>(out);
}